// round 16
// baseline (speedup 1.0000x reference)
#include <cuda_runtime.h>
#include <cuda_fp16.h>
#include <cstdint>

// Problem constants
#define BDIM   1024
#define BRANK  64
#define BHEADS 16
#define BB     2
#define BT     2048

// ---------------------------------------------------------------------------
// Scratch (device globals) — all operands single fp16
// ---------------------------------------------------------------------------
__device__ __align__(256) __half g_e[(size_t)BB * BHEADS * BT * BT];     // E = exp(scores)
__device__ __align__(256) float g_part[(size_t)BB * BHEADS * BT * 16];
__device__ __align__(256) __half g_xh[(size_t)BB * BT * BDIM];           // x row-major
__device__ __align__(256) __half g_qkh[(size_t)2 * BHEADS * BRANK * BDIM]; // [Q;K] stacked
__device__ __align__(256) __half g_xq[(size_t)BB * BT * BHEADS * BRANK];
__device__ __align__(256) __half g_xk[(size_t)BB * BT * BHEADS * BRANK];
__device__ __align__(256) __half g_xt[(size_t)BB * BDIM * BT];           // x^T per batch
__device__ __align__(256) __half g_ctx[(size_t)BB * BT * BHEADS * BDIM];
__device__ __align__(256) __half g_vot[(size_t)BDIM * BHEADS * BDIM];    // VO^T

// ---------------------------------------------------------------------------
// Helpers
// ---------------------------------------------------------------------------
__device__ __forceinline__ uint32_t smem_u32(const void* p) {
    return (uint32_t)__cvta_generic_to_shared(p);
}

#define CP16(s, g) asm volatile("cp.async.cg.shared.global [%0], [%1], 16;" :: "r"(s), "l"(g))

__device__ __forceinline__ void ldsm4(uint32_t* r, uint32_t addr) {
    asm volatile("ldmatrix.sync.aligned.m8n8.x4.shared.b16 {%0,%1,%2,%3}, [%4];"
        : "=r"(r[0]), "=r"(r[1]), "=r"(r[2]), "=r"(r[3]) : "r"(addr));
}

__device__ __forceinline__ void mma16816h(float* c, const uint32_t* a, const uint32_t* b) {
    asm volatile("mma.sync.aligned.m16n8k16.row.col.f32.f16.f16.f32 "
        "{%0,%1,%2,%3}, {%4,%5,%6,%7}, {%8,%9}, {%0,%1,%2,%3};"
        : "+f"(c[0]), "+f"(c[1]), "+f"(c[2]), "+f"(c[3])
        : "r"(a[0]), "r"(a[1]), "r"(a[2]), "r"(a[3]), "r"(b[0]), "r"(b[1]));
}

template <int N>
__device__ __forceinline__ void cp_wait() {
    asm volatile("cp.async.wait_group %0;" :: "n"(N) : "memory");
}

// ---------------------------------------------------------------------------
// Fused Q+K fp32 -> fp16 convert: z=0 -> Q, z=1 -> K, dest contiguous halves
// ---------------------------------------------------------------------------
__global__ __launch_bounds__(256)
void convert_qk(const float* __restrict__ Q, const float* __restrict__ K,
                __half* __restrict__ oh, long long n4)
{
    const long long i = (long long)blockIdx.x * 256 + threadIdx.x;
    if (i >= n4) return;
    const float* src = blockIdx.y ? K : Q;
    __half* dst = oh + (long long)blockIdx.y * n4 * 4;
    float4 v = reinterpret_cast<const float4*>(src)[i];
    __half2 h01, h23;
    h01.x = __float2half(v.x); h01.y = __float2half(v.y);
    h23.x = __float2half(v.z); h23.y = __float2half(v.w);
    reinterpret_cast<__half2*>(dst)[2 * i + 0] = h01;
    reinterpret_cast<__half2*>(dst)[2 * i + 1] = h23;
}

// ---------------------------------------------------------------------------
// Transpose (+ optional row-major copy) fp32 -> fp16.
// 64x32 tile, 256 threads. float2 loads; transposed stores are half2 with
// warp = column, lane = row-pair -> 128 B contiguous run per warp.
// orow may be null.
// ---------------------------------------------------------------------------
__global__ __launch_bounds__(256)
void transpose_h(const float* __restrict__ in, long long inBS, int C,
                 __half* __restrict__ orow,
                 __half* __restrict__ ot, int oLd, long long oBS)
{
    __shared__ float tile[64][33];
    const int z = blockIdx.z;
    const float* ip = in + (long long)z * inBS;
    const int c0 = blockIdx.x * 32;
    const int r0 = blockIdx.y * 64;
    const int tid = threadIdx.x;

    {
        const int tx = tid & 15;          // col pair
        const int ty = tid >> 4;          // 0..15
#pragma unroll
        for (int i = 0; i < 4; i++) {
            const int r = ty + 16 * i;    // 0..63
            const float2 v = *reinterpret_cast<const float2*>(
                ip + (long long)(r0 + r) * C + c0 + 2 * tx);
            tile[r][2 * tx + 0] = v.x;
            tile[r][2 * tx + 1] = v.y;
            if (orow) {
                __half2 h;
                h.x = __float2half(v.x);
                h.y = __float2half(v.y);
                *reinterpret_cast<__half2*>(
                    orow + (long long)z * inBS + (long long)(r0 + r) * C + c0 + 2 * tx) = h;
            }
        }
    }
    __syncthreads();

    {
        const int w    = tid >> 5;
        const int lane = tid & 31;
        const long long ob = (long long)z * oBS;
#pragma unroll
        for (int j = 0; j < 4; j++) {
            const int c = w + 8 * j;      // 0..31
            __half2 h;
            h.x = __float2half(tile[2 * lane + 0][c]);
            h.y = __float2half(tile[2 * lane + 1][c]);
            *reinterpret_cast<__half2*>(
                ot + ob + (long long)(c0 + c) * oLd + r0 + 2 * lane) = h;
        }
    }
}

// ---------------------------------------------------------------------------
// fp16 1-term HMMA GEMM, 3-stage cp.async pipeline, 128x128 tile, KC=64.
// C = A @ B^T, fp32 accumulate. A: [M][K] rows (lda), B: [N][K] rows (ldb).
// STAGE==1: epilogue fp16; ncol<1024 -> C1=xq else C2=xk (ldc).
// STAGE==3: z=(b,h); epilogue exp2(acc*alpha) -> fp16 E + quantized row sums
//           written to Cf (16 partials per row). alpha = (1/32)*log2(e).
// STAGE==4: A=E flat; B=xT per batch; prologue reduces partials (Rpart) to
//           1/rowsum in smem; epilogue *= rinv, fp16 ctx scatter.
// STAGE==5: epilogue fp32 -> Cf.
// ---------------------------------------------------------------------------
#define HTM 128
#define HTN 128
#define HTK 64

#define BUFSTRIDE 32768              // 2 tiles x 16KB
#define BHI_O 16384
#define HMMA_SMEM (3 * BUFSTRIDE)    // 96 KB

template <int STAGE>
__global__ __launch_bounds__(256, 2)
void hmma_gemm(const __half* __restrict__ A, int lda,
               const __half* __restrict__ B, int ldb,
               float* __restrict__ Cf,
               __half* __restrict__ C1, __half* __restrict__ C2,
               const float* __restrict__ Rpart,
               int ldc, int K, float alpha)
{
    extern __shared__ char smem[];
    __shared__ float srow[2][HTM];
    const uint32_t sb = smem_u32(smem);
    const int tid  = threadIdx.x;
    const int wid  = tid >> 5;
    const int lane = tid & 31;
    const int mw = wid & 3;
    const int nw = wid >> 2;

    const long long m0 = (long long)blockIdx.y * HTM;
    const int n0 = blockIdx.x * HTN;

    const __half *Ab, *Bb;
    if (STAGE == 3) {
        const int z = blockIdx.z;
        const int b = z >> 4;
        const int h = z & 15;
        Ab = A + ((long long)b * BT + m0) * lda + h * BRANK;
        Bb = B + ((long long)b * BT + n0) * ldb + h * BRANK;
    } else if (STAGE == 4) {
        const long long b = m0 >> 15;       // 32768 flat rows per batch
        Ab = A + m0 * lda;
        Bb = B + b * ((long long)BDIM * BT) + (long long)n0 * ldb;
    } else {
        Ab = A + m0 * lda;
        Bb = B + (long long)n0 * ldb;
    }

    // STAGE 4 prologue: fold reduce_inv — 1/rowsum for this CTA's 128 rows.
    // Visibility to all threads ordered by the first __syncthreads below.
    if (STAGE == 4) {
        if (tid < HTM) {
            const float4* p = reinterpret_cast<const float4*>(Rpart + (m0 + tid) * 16);
            float4 a = p[0], b4 = p[1], c4 = p[2], d4 = p[3];
            float s = ((a.x + a.y) + (a.z + a.w)) + ((b4.x + b4.y) + (b4.z + b4.w))
                    + ((c4.x + c4.y) + (c4.z + c4.w)) + ((d4.x + d4.y) + (d4.z + d4.w));
            srow[0][tid] = 1.0f / s;
        }
    }

    float acc[2][8][4];
#pragma unroll
    for (int i = 0; i < 2; i++)
#pragma unroll
        for (int f = 0; f < 8; f++)
#pragma unroll
            for (int e = 0; e < 4; e++) acc[i][f][e] = 0.0f;

    const int NC = K / HTK;

    auto load_chunk = [&](int c, int buf) {
        const long long kg = (long long)c * HTK;
        const uint32_t bb = sb + buf * BUFSTRIDE;
#pragma unroll
        for (int i = 0; i < 4; i++) {
            const int idx = tid + i * 256;
            const int r  = idx >> 3;
            const int ck = idx & 7;
            const uint32_t so = (uint32_t)(r * 128 + ((ck ^ (r & 7)) << 4));
            const long long ga = (long long)r * lda + kg + ck * 8;
            const long long gb = (long long)r * ldb + kg + ck * 8;
            CP16(bb + so, (const void*)(Ab + ga));
            CP16(bb + BHI_O + so, (const void*)(Bb + gb));
        }
        asm volatile("cp.async.commit_group;" ::: "memory");
    };

    load_chunk(0, 0);
    if (NC > 1) load_chunk(1, 1);

    for (int c = 0; c < NC; c++) {
        if (c + 2 < NC) load_chunk(c + 2, (c + 2) % 3);
        const int pend = (NC - 1 - c >= 2) ? 2 : (NC - 1 - c);
        if (pend == 2)      cp_wait<2>();
        else if (pend == 1) cp_wait<1>();
        else                cp_wait<0>();
        __syncthreads();

        const uint32_t ab = sb + (c % 3) * BUFSTRIDE;
#pragma unroll
        for (int ks = 0; ks < 4; ks++) {
            uint32_t ah[2][4], bh[4][4];
#pragma unroll
            for (int i = 0; i < 2; i++) {
                const int r  = mw * 32 + i * 16 + (lane & 15);
                const int ck = ks * 2 + (lane >> 4);
                const uint32_t off = (uint32_t)(r * 128 + ((ck ^ (r & 7)) << 4));
                ldsm4(ah[i], ab + off);
            }
#pragma unroll
            for (int j = 0; j < 4; j++) {
                const int r  = nw * 64 + j * 16 + (lane & 7) + ((lane >> 4) & 1) * 8;
                const int ck = ks * 2 + ((lane >> 3) & 1);
                const uint32_t off = (uint32_t)(r * 128 + ((ck ^ (r & 7)) << 4));
                ldsm4(bh[j], ab + BHI_O + off);
            }
#pragma unroll
            for (int i = 0; i < 2; i++)
#pragma unroll
                for (int f = 0; f < 8; f++)
                    mma16816h(acc[i][f], ah[i], &bh[f >> 1][(f & 1) * 2]);
        }
        __syncthreads();
    }

    // Epilogue
#pragma unroll
    for (int i = 0; i < 2; i++) {
#pragma unroll
        for (int hr = 0; hr < 2; hr++) {
            const int rl = mw * 32 + i * 16 + hr * 8 + (lane >> 2);   // local row
            const long long mg = m0 + rl;
            const int ncol = n0 + nw * 64 + (lane & 3) * 2;
            if (STAGE == 5) {
                float* dst = Cf + mg * ldc + ncol;
#pragma unroll
                for (int f = 0; f < 8; f++) {
                    float2 v;
                    v.x = acc[i][f][hr * 2 + 0];
                    v.y = acc[i][f][hr * 2 + 1];
                    *reinterpret_cast<float2*>(dst + f * 8) = v;
                }
            } else if (STAGE == 3) {
                // E = 2^(score*alpha) -> fp16; rowsum of QUANTIZED values
                const long long orow = (long long)blockIdx.z * BT * BT + mg * ldc + ncol;
                float part = 0.0f;
#pragma unroll
                for (int f = 0; f < 8; f++) {
                    const float e0 = exp2f(acc[i][f][hr * 2 + 0] * alpha);
                    const float e1 = exp2f(acc[i][f][hr * 2 + 1] * alpha);
                    __half2 hv;
                    hv.x = __float2half(e0);
                    hv.y = __float2half(e1);
                    part += __half2float(hv.x) + __half2float(hv.y);
                    *reinterpret_cast<__half2*>(C1 + orow + f * 8) = hv;
                }
                part += __shfl_xor_sync(0xffffffffu, part, 1);
                part += __shfl_xor_sync(0xffffffffu, part, 2);
                if ((lane & 3) == 0)
                    srow[nw][rl] = part;
            } else if (STAGE == 1) {
                const bool isK = (ncol >= 1024);
                __half* D = isK ? C2 : C1;
                const long long orow = mg * ldc + (ncol - (isK ? 1024 : 0));
#pragma unroll
                for (int f = 0; f < 8; f++) {
                    __half2 hv;
                    hv.x = __float2half(acc[i][f][hr * 2 + 0]);
                    hv.y = __float2half(acc[i][f][hr * 2 + 1]);
                    *reinterpret_cast<__half2*>(D + orow + f * 8) = hv;
                }
            } else { // STAGE == 4 : ctx fp16 scatter, rinv from prologue smem
                const float rs = srow[0][rl];
                const int b = (int)(mg >> 15);
                const int h = (int)((mg >> 11) & 15);
                const int t = (int)(mg & 2047);
                const long long orow =
                    ((long long)b * BT + t) * ((long long)BHEADS * BDIM) +
                    (long long)h * BDIM + ncol;
#pragma unroll
                for (int f = 0; f < 8; f++) {
                    __half2 hv;
                    hv.x = __float2half(acc[i][f][hr * 2 + 0] * rs);
                    hv.y = __float2half(acc[i][f][hr * 2 + 1] * rs);
                    *reinterpret_cast<__half2*>(C1 + orow + f * 8) = hv;
                }
            }
        }
    }

    if (STAGE == 3) {
        __syncthreads();
        if (tid < HTM) {
            const float s = srow[0][tid] + srow[1][tid];
            Cf[((long long)blockIdx.z * BT + m0 + tid) * 16 + blockIdx.x] = s;
        }
    }
}

// ---------------------------------------------------------------------------
// Launch
// ---------------------------------------------------------------------------
extern "C" void kernel_launch(void* const* d_in, const int* in_sizes, int n_in,
                              void* d_out, int out_size)
{
    const float* x  = (const float*)d_in[0];
    const float* Q  = (const float*)d_in[1];
    const float* K  = (const float*)d_in[2];
    const float* VO = (const float*)d_in[3];
    float* out = (float*)d_out;

    float *part;
    __half *e, *xh, *qkh, *xq, *xk, *xt, *ctx, *vot;
    cudaGetSymbolAddress((void**)&part, g_part);
    cudaGetSymbolAddress((void**)&e,    g_e);
    cudaGetSymbolAddress((void**)&xh,   g_xh);
    cudaGetSymbolAddress((void**)&qkh,  g_qkh);
    cudaGetSymbolAddress((void**)&xq,   g_xq);
    cudaGetSymbolAddress((void**)&xk,   g_xk);
    cudaGetSymbolAddress((void**)&xt,   g_xt);
    cudaGetSymbolAddress((void**)&ctx,  g_ctx);
    cudaGetSymbolAddress((void**)&vot,  g_vot);

    cudaFuncSetAttribute(hmma_gemm<1>, cudaFuncAttributeMaxDynamicSharedMemorySize, HMMA_SMEM);
    cudaFuncSetAttribute(hmma_gemm<3>, cudaFuncAttributeMaxDynamicSharedMemorySize, HMMA_SMEM);
    cudaFuncSetAttribute(hmma_gemm<4>, cudaFuncAttributeMaxDynamicSharedMemorySize, HMMA_SMEM);
    cudaFuncSetAttribute(hmma_gemm<5>, cudaFuncAttributeMaxDynamicSharedMemorySize, HMMA_SMEM);

    const int MBT = BB * BT;                  // 4096
    const int HR  = BHEADS * BRANK;           // 1024
    const int HD  = BHEADS * BDIM;            // 16384

    // fp16 prep: x (row + transposed, single read), Q+K fused convert, VO transpose
    transpose_h<<<dim3(BDIM / 32, BT / 64, BB), 256>>>(
        x, (long long)BT * BDIM, BDIM, xh, xt, BT, (long long)BDIM * BT);
    convert_qk<<<dim3(HR * BDIM / 4 / 256, 2), 256>>>(Q, K, qkh, (long long)HR * BDIM / 4);
    transpose_h<<<dim3(BDIM / 32, BDIM / 64, BHEADS), 256>>>(
        VO, (long long)BDIM * BDIM, BDIM, nullptr, vot, HD, (long long)BDIM);

    // 1+2) [xq | xk] = x @ [Q;K]^T   M=4096, N=2048, K=1024
    hmma_gemm<1><<<dim3(2 * HR / HTN, MBT / HTM), 256, HMMA_SMEM>>>(
        xh, BDIM, qkh, BDIM, nullptr, xq, xk, nullptr, HR, BDIM, 1.0f);
    // 3) E = exp(xq @ xk^T / 32) per (b,h) + quantized row sums   M=N=2048, K=64
    //    alpha folded with log2(e) for exp2f
    hmma_gemm<3><<<dim3(BT / HTN, BT / HTM, BB * BHEADS), 256, HMMA_SMEM>>>(
        xq, HR, xk, HR, part, e, nullptr, nullptr, BT, BRANK,
        0.03125f * 1.4426950408889634f);
    // 4) ctx = (E @ x) * rinv  (rinv folded into prologue)  M=65536 flat, N=1024, K=2048
    hmma_gemm<4><<<dim3(BDIM / HTN, (BB * BHEADS * BT) / HTM), 256, HMMA_SMEM>>>(
        e, BT, xt, BT, nullptr, ctx, nullptr, part, 0, BT, 1.0f);
    // 5) out = ctx @ VO   M=4096, N=1024, K=16384
    hmma_gemm<5><<<dim3(BDIM / HTN, MBT / HTM), 256, HMMA_SMEM>>>(
        ctx, HD, vot, HD, out, nullptr, nullptr, nullptr, BDIM, HD, 1.0f);
}

// round 17
// speedup vs baseline: 1.0081x; 1.0081x over previous
#include <cuda_runtime.h>
#include <cuda_fp16.h>
#include <cstdint>

// Problem constants
#define BDIM   1024
#define BRANK  64
#define BHEADS 16
#define BB     2
#define BT     2048

// ---------------------------------------------------------------------------
// Scratch (device globals) — all operands single fp16
// ---------------------------------------------------------------------------
__device__ __align__(256) __half g_e[(size_t)BB * BHEADS * BT * BT];     // E = exp(scores)
__device__ __align__(256) float g_part[(size_t)BB * BHEADS * BT * 16];
__device__ __align__(256) __half g_xh[(size_t)BB * BT * BDIM];           // x row-major
__device__ __align__(256) __half g_qkh[(size_t)2 * BHEADS * BRANK * BDIM]; // [Q;K] stacked
__device__ __align__(256) __half g_xq[(size_t)BB * BT * BHEADS * BRANK];
__device__ __align__(256) __half g_xk[(size_t)BB * BT * BHEADS * BRANK];
__device__ __align__(256) __half g_xt[(size_t)BB * BDIM * BT];           // x^T per batch
__device__ __align__(256) __half g_ctx[(size_t)BB * BT * BHEADS * BDIM];
__device__ __align__(256) __half g_vot[(size_t)BDIM * BHEADS * BDIM];    // VO^T

// ---------------------------------------------------------------------------
// Helpers
// ---------------------------------------------------------------------------
__device__ __forceinline__ uint32_t smem_u32(const void* p) {
    return (uint32_t)__cvta_generic_to_shared(p);
}

#define CP16(s, g) asm volatile("cp.async.cg.shared.global [%0], [%1], 16;" :: "r"(s), "l"(g))

__device__ __forceinline__ void ldsm4(uint32_t* r, uint32_t addr) {
    asm volatile("ldmatrix.sync.aligned.m8n8.x4.shared.b16 {%0,%1,%2,%3}, [%4];"
        : "=r"(r[0]), "=r"(r[1]), "=r"(r[2]), "=r"(r[3]) : "r"(addr));
}

__device__ __forceinline__ void mma16816h(float* c, const uint32_t* a, const uint32_t* b) {
    asm volatile("mma.sync.aligned.m16n8k16.row.col.f32.f16.f16.f32 "
        "{%0,%1,%2,%3}, {%4,%5,%6,%7}, {%8,%9}, {%0,%1,%2,%3};"
        : "+f"(c[0]), "+f"(c[1]), "+f"(c[2]), "+f"(c[3])
        : "r"(a[0]), "r"(a[1]), "r"(a[2]), "r"(a[3]), "r"(b[0]), "r"(b[1]));
}

template <int N>
__device__ __forceinline__ void cp_wait() {
    asm volatile("cp.async.wait_group %0;" :: "n"(N) : "memory");
}

// ---------------------------------------------------------------------------
// Fused Q+K fp32 -> fp16 convert: y=0 -> Q, y=1 -> K, dest contiguous halves
// ---------------------------------------------------------------------------
__global__ __launch_bounds__(256)
void convert_qk(const float* __restrict__ Q, const float* __restrict__ K,
                __half* __restrict__ oh, long long n4)
{
    const long long i = (long long)blockIdx.x * 256 + threadIdx.x;
    if (i >= n4) return;
    const float* src = blockIdx.y ? K : Q;
    __half* dst = oh + (long long)blockIdx.y * n4 * 4;
    float4 v = reinterpret_cast<const float4*>(src)[i];
    __half2 h01, h23;
    h01.x = __float2half(v.x); h01.y = __float2half(v.y);
    h23.x = __float2half(v.z); h23.y = __float2half(v.w);
    reinterpret_cast<__half2*>(dst)[2 * i + 0] = h01;
    reinterpret_cast<__half2*>(dst)[2 * i + 1] = h23;
}

// ---------------------------------------------------------------------------
// Transpose (+ optional row-major copy) fp32 -> fp16.
// 64x32 tile, 256 threads. float2 loads; transposed stores are half2 with
// warp = column, lane = row-pair -> 128 B contiguous run per warp.
// orow may be null.
// ---------------------------------------------------------------------------
__global__ __launch_bounds__(256)
void transpose_h(const float* __restrict__ in, long long inBS, int C,
                 __half* __restrict__ orow,
                 __half* __restrict__ ot, int oLd, long long oBS)
{
    __shared__ float tile[64][33];
    const int z = blockIdx.z;
    const float* ip = in + (long long)z * inBS;
    const int c0 = blockIdx.x * 32;
    const int r0 = blockIdx.y * 64;
    const int tid = threadIdx.x;

    {
        const int tx = tid & 15;          // col pair
        const int ty = tid >> 4;          // 0..15
#pragma unroll
        for (int i = 0; i < 4; i++) {
            const int r = ty + 16 * i;    // 0..63
            const float2 v = *reinterpret_cast<const float2*>(
                ip + (long long)(r0 + r) * C + c0 + 2 * tx);
            tile[r][2 * tx + 0] = v.x;
            tile[r][2 * tx + 1] = v.y;
            if (orow) {
                __half2 h;
                h.x = __float2half(v.x);
                h.y = __float2half(v.y);
                *reinterpret_cast<__half2*>(
                    orow + (long long)z * inBS + (long long)(r0 + r) * C + c0 + 2 * tx) = h;
            }
        }
    }
    __syncthreads();

    {
        const int w    = tid >> 5;
        const int lane = tid & 31;
        const long long ob = (long long)z * oBS;
#pragma unroll
        for (int j = 0; j < 4; j++) {
            const int c = w + 8 * j;      // 0..31
            __half2 h;
            h.x = __float2half(tile[2 * lane + 0][c]);
            h.y = __float2half(tile[2 * lane + 1][c]);
            *reinterpret_cast<__half2*>(
                ot + ob + (long long)(c0 + c) * oLd + r0 + 2 * lane) = h;
        }
    }
}

// ---------------------------------------------------------------------------
// fp16 1-term HMMA GEMM, 3-stage cp.async ring, SINGLE sync per K-chunk.
// Pattern per chunk c: cp_wait(data c) -> __syncthreads -> issue load(c+2)
// -> compute(c). Safety: buffer (c+2)%3 == (c-1)%3 was last read in compute
// c-1, and every thread at the top sync of c has finished compute c-1.
// C = A @ B^T, fp32 accumulate. A: [M][K] rows (lda), B: [N][K] rows (ldb).
// STAGE==1: epilogue fp16; ncol<1024 -> C1=xq else C2=xk (ldc).
// STAGE==3: z=(b,h); epilogue exp2(acc*alpha) -> fp16 E + quantized row sums.
// STAGE==4: A=E flat; B=xT per batch; prologue reduces partials (Rpart) to
//           1/rowsum in smem; epilogue *= rinv, fp16 ctx scatter.
// STAGE==5: epilogue fp32 -> Cf.
// ---------------------------------------------------------------------------
#define HTM 128
#define HTN 128
#define HTK 64

#define BUFSTRIDE 32768              // 2 tiles x 16KB
#define BHI_O 16384
#define HMMA_SMEM (3 * BUFSTRIDE)    // 96 KB

template <int STAGE>
__global__ __launch_bounds__(256, 2)
void hmma_gemm(const __half* __restrict__ A, int lda,
               const __half* __restrict__ B, int ldb,
               float* __restrict__ Cf,
               __half* __restrict__ C1, __half* __restrict__ C2,
               const float* __restrict__ Rpart,
               int ldc, int K, float alpha)
{
    extern __shared__ char smem[];
    __shared__ float srow[2][HTM];
    const uint32_t sb = smem_u32(smem);
    const int tid  = threadIdx.x;
    const int wid  = tid >> 5;
    const int lane = tid & 31;
    const int mw = wid & 3;
    const int nw = wid >> 2;

    const long long m0 = (long long)blockIdx.y * HTM;
    const int n0 = blockIdx.x * HTN;

    const __half *Ab, *Bb;
    if (STAGE == 3) {
        const int z = blockIdx.z;
        const int b = z >> 4;
        const int h = z & 15;
        Ab = A + ((long long)b * BT + m0) * lda + h * BRANK;
        Bb = B + ((long long)b * BT + n0) * ldb + h * BRANK;
    } else if (STAGE == 4) {
        const long long b = m0 >> 15;       // 32768 flat rows per batch
        Ab = A + m0 * lda;
        Bb = B + b * ((long long)BDIM * BT) + (long long)n0 * ldb;
    } else {
        Ab = A + m0 * lda;
        Bb = B + (long long)n0 * ldb;
    }

    // STAGE 4 prologue: fold reduce_inv — 1/rowsum for this CTA's 128 rows.
    if (STAGE == 4) {
        if (tid < HTM) {
            const float4* p = reinterpret_cast<const float4*>(Rpart + (m0 + tid) * 16);
            float4 a = p[0], b4 = p[1], c4 = p[2], d4 = p[3];
            float s = ((a.x + a.y) + (a.z + a.w)) + ((b4.x + b4.y) + (b4.z + b4.w))
                    + ((c4.x + c4.y) + (c4.z + c4.w)) + ((d4.x + d4.y) + (d4.z + d4.w));
            srow[0][tid] = 1.0f / s;
        }
    }

    float acc[2][8][4];
#pragma unroll
    for (int i = 0; i < 2; i++)
#pragma unroll
        for (int f = 0; f < 8; f++)
#pragma unroll
            for (int e = 0; e < 4; e++) acc[i][f][e] = 0.0f;

    const int NC = K / HTK;

    auto load_chunk = [&](int c, int buf) {
        const long long kg = (long long)c * HTK;
        const uint32_t bb = sb + buf * BUFSTRIDE;
#pragma unroll
        for (int i = 0; i < 4; i++) {
            const int idx = tid + i * 256;
            const int r  = idx >> 3;
            const int ck = idx & 7;
            const uint32_t so = (uint32_t)(r * 128 + ((ck ^ (r & 7)) << 4));
            const long long ga = (long long)r * lda + kg + ck * 8;
            const long long gb = (long long)r * ldb + kg + ck * 8;
            CP16(bb + so, (const void*)(Ab + ga));
            CP16(bb + BHI_O + so, (const void*)(Bb + gb));
        }
        asm volatile("cp.async.commit_group;" ::: "memory");
    };

    load_chunk(0, 0);
    if (NC > 1) load_chunk(1, 1);

    for (int c = 0; c < NC; c++) {
        // wait for chunk c's data; outstanding groups = {c, c+1}
        if (c + 1 < NC) cp_wait<1>();
        else            cp_wait<0>();
        __syncthreads();
        // safe to overwrite buffer (c+2)%3 == (c-1)%3: all threads passed the
        // sync above, hence finished compute of chunk c-1.
        if (c + 2 < NC) load_chunk(c + 2, (c + 2) % 3);

        const uint32_t ab = sb + (c % 3) * BUFSTRIDE;
#pragma unroll
        for (int ks = 0; ks < 4; ks++) {
            uint32_t ah[2][4], bh[4][4];
#pragma unroll
            for (int i = 0; i < 2; i++) {
                const int r  = mw * 32 + i * 16 + (lane & 15);
                const int ck = ks * 2 + (lane >> 4);
                const uint32_t off = (uint32_t)(r * 128 + ((ck ^ (r & 7)) << 4));
                ldsm4(ah[i], ab + off);
            }
#pragma unroll
            for (int j = 0; j < 4; j++) {
                const int r  = nw * 64 + j * 16 + (lane & 7) + ((lane >> 4) & 1) * 8;
                const int ck = ks * 2 + ((lane >> 3) & 1);
                const uint32_t off = (uint32_t)(r * 128 + ((ck ^ (r & 7)) << 4));
                ldsm4(bh[j], ab + BHI_O + off);
            }
#pragma unroll
            for (int i = 0; i < 2; i++)
#pragma unroll
                for (int f = 0; f < 8; f++)
                    mma16816h(acc[i][f], ah[i], &bh[f >> 1][(f & 1) * 2]);
        }
    }

    // Epilogue
#pragma unroll
    for (int i = 0; i < 2; i++) {
#pragma unroll
        for (int hr = 0; hr < 2; hr++) {
            const int rl = mw * 32 + i * 16 + hr * 8 + (lane >> 2);   // local row
            const long long mg = m0 + rl;
            const int ncol = n0 + nw * 64 + (lane & 3) * 2;
            if (STAGE == 5) {
                float* dst = Cf + mg * ldc + ncol;
#pragma unroll
                for (int f = 0; f < 8; f++) {
                    float2 v;
                    v.x = acc[i][f][hr * 2 + 0];
                    v.y = acc[i][f][hr * 2 + 1];
                    *reinterpret_cast<float2*>(dst + f * 8) = v;
                }
            } else if (STAGE == 3) {
                // E = 2^(score*alpha) -> fp16; rowsum of QUANTIZED values
                const long long orow = (long long)blockIdx.z * BT * BT + mg * ldc + ncol;
                float part = 0.0f;
#pragma unroll
                for (int f = 0; f < 8; f++) {
                    const float e0 = exp2f(acc[i][f][hr * 2 + 0] * alpha);
                    const float e1 = exp2f(acc[i][f][hr * 2 + 1] * alpha);
                    __half2 hv;
                    hv.x = __float2half(e0);
                    hv.y = __float2half(e1);
                    part += __half2float(hv.x) + __half2float(hv.y);
                    *reinterpret_cast<__half2*>(C1 + orow + f * 8) = hv;
                }
                part += __shfl_xor_sync(0xffffffffu, part, 1);
                part += __shfl_xor_sync(0xffffffffu, part, 2);
                if ((lane & 3) == 0)
                    srow[nw][rl] = part;
            } else if (STAGE == 1) {
                const bool isK = (ncol >= 1024);
                __half* D = isK ? C2 : C1;
                const long long orow = mg * ldc + (ncol - (isK ? 1024 : 0));
#pragma unroll
                for (int f = 0; f < 8; f++) {
                    __half2 hv;
                    hv.x = __float2half(acc[i][f][hr * 2 + 0]);
                    hv.y = __float2half(acc[i][f][hr * 2 + 1]);
                    *reinterpret_cast<__half2*>(D + orow + f * 8) = hv;
                }
            } else { // STAGE == 4 : ctx fp16 scatter, rinv from prologue smem
                const float rs = srow[0][rl];
                const int b = (int)(mg >> 15);
                const int h = (int)((mg >> 11) & 15);
                const int t = (int)(mg & 2047);
                const long long orow =
                    ((long long)b * BT + t) * ((long long)BHEADS * BDIM) +
                    (long long)h * BDIM + ncol;
#pragma unroll
                for (int f = 0; f < 8; f++) {
                    __half2 hv;
                    hv.x = __float2half(acc[i][f][hr * 2 + 0] * rs);
                    hv.y = __float2half(acc[i][f][hr * 2 + 1] * rs);
                    *reinterpret_cast<__half2*>(C1 + orow + f * 8) = hv;
                }
            }
        }
    }

    if (STAGE == 3) {
        __syncthreads();
        if (tid < HTM) {
            const float s = srow[0][tid] + srow[1][tid];
            Cf[((long long)blockIdx.z * BT + m0 + tid) * 16 + blockIdx.x] = s;
        }
    }
}

// ---------------------------------------------------------------------------
// Launch
// ---------------------------------------------------------------------------
extern "C" void kernel_launch(void* const* d_in, const int* in_sizes, int n_in,
                              void* d_out, int out_size)
{
    const float* x  = (const float*)d_in[0];
    const float* Q  = (const float*)d_in[1];
    const float* K  = (const float*)d_in[2];
    const float* VO = (const float*)d_in[3];
    float* out = (float*)d_out;

    float *part;
    __half *e, *xh, *qkh, *xq, *xk, *xt, *ctx, *vot;
    cudaGetSymbolAddress((void**)&part, g_part);
    cudaGetSymbolAddress((void**)&e,    g_e);
    cudaGetSymbolAddress((void**)&xh,   g_xh);
    cudaGetSymbolAddress((void**)&qkh,  g_qkh);
    cudaGetSymbolAddress((void**)&xq,   g_xq);
    cudaGetSymbolAddress((void**)&xk,   g_xk);
    cudaGetSymbolAddress((void**)&xt,   g_xt);
    cudaGetSymbolAddress((void**)&ctx,  g_ctx);
    cudaGetSymbolAddress((void**)&vot,  g_vot);

    cudaFuncSetAttribute(hmma_gemm<1>, cudaFuncAttributeMaxDynamicSharedMemorySize, HMMA_SMEM);
    cudaFuncSetAttribute(hmma_gemm<3>, cudaFuncAttributeMaxDynamicSharedMemorySize, HMMA_SMEM);
    cudaFuncSetAttribute(hmma_gemm<4>, cudaFuncAttributeMaxDynamicSharedMemorySize, HMMA_SMEM);
    cudaFuncSetAttribute(hmma_gemm<5>, cudaFuncAttributeMaxDynamicSharedMemorySize, HMMA_SMEM);

    const int MBT = BB * BT;                  // 4096
    const int HR  = BHEADS * BRANK;           // 1024
    const int HD  = BHEADS * BDIM;            // 16384

    // fp16 prep: x (row + transposed, single read), Q+K fused convert, VO transpose
    transpose_h<<<dim3(BDIM / 32, BT / 64, BB), 256>>>(
        x, (long long)BT * BDIM, BDIM, xh, xt, BT, (long long)BDIM * BT);
    convert_qk<<<dim3(HR * BDIM / 4 / 256, 2), 256>>>(Q, K, qkh, (long long)HR * BDIM / 4);
    transpose_h<<<dim3(BDIM / 32, BDIM / 64, BHEADS), 256>>>(
        VO, (long long)BDIM * BDIM, BDIM, nullptr, vot, HD, (long long)BDIM);

    // 1+2) [xq | xk] = x @ [Q;K]^T   M=4096, N=2048, K=1024
    hmma_gemm<1><<<dim3(2 * HR / HTN, MBT / HTM), 256, HMMA_SMEM>>>(
        xh, BDIM, qkh, BDIM, nullptr, xq, xk, nullptr, HR, BDIM, 1.0f);
    // 3) E = exp(xq @ xk^T / 32) per (b,h) + quantized row sums   M=N=2048, K=64
    hmma_gemm<3><<<dim3(BT / HTN, BT / HTM, BB * BHEADS), 256, HMMA_SMEM>>>(
        xq, HR, xk, HR, part, e, nullptr, nullptr, BT, BRANK,
        0.03125f * 1.4426950408889634f);
    // 4) ctx = (E @ x) * rinv  (rinv folded into prologue)  M=65536 flat, N=1024, K=2048
    hmma_gemm<4><<<dim3(BDIM / HTN, (BB * BHEADS * BT) / HTM), 256, HMMA_SMEM>>>(
        e, BT, xt, BT, nullptr, ctx, nullptr, part, 0, BT, 1.0f);
    // 5) out = ctx @ VO   M=4096, N=1024, K=16384
    hmma_gemm<5><<<dim3(BDIM / HTN, MBT / HTM), 256, HMMA_SMEM>>>(
        ctx, HD, vot, HD, out, nullptr, nullptr, nullptr, BDIM, HD, 1.0f);
}